// round 3
// baseline (speedup 1.0000x reference)
#include <cuda_runtime.h>

#define BH   16
#define LQ   512
#define LK   512
#define DD   64
#define TQ   32
#define TK   128
#define WKP  68   // padded wk row (floats): 272B, 16B-aligned, conflict-free phases

// Projected tensors, both row-major [row][d] (device globals: no allocation).
__device__ float g_Wq[BH * LQ * DD];
__device__ float g_Wk[BH * LK * DD];

// ---------------------------------------------------------------------------
// 2 fp32 adds in one FMA-pipe op (operands are natural register pairs).
// ---------------------------------------------------------------------------
__device__ __forceinline__ double add_f32x2(double a, double b) {
    double r;
    asm("add.rn.f32x2 %0, %1, %2;" : "=d"(r) : "d"(a), "d"(b));
    return r;
}

// ---------------------------------------------------------------------------
// 2 tanhs in ONE MUFU op: f32x2 sum -> f16x2 -> tanh.approx.f16x2 -> 2x f32.
// ---------------------------------------------------------------------------
__device__ __forceinline__ float2 tanh2_f16(double s) {
    float2 r;
    asm("{\n\t"
        ".reg .f32 s0, s1;\n\t"
        ".reg .b32 hp;\n\t"
        ".reg .f16 h0, h1;\n\t"
        "mov.b64 {s0, s1}, %2;\n\t"
        "cvt.rn.f16x2.f32 hp, s1, s0;\n\t"   // hi=s1, lo=s0
        "tanh.approx.f16x2 hp, hp;\n\t"
        "mov.b32 {h0, h1}, hp;\n\t"
        "cvt.f32.f16 %0, h0;\n\t"
        "cvt.f32.f16 %1, h1;\n\t"
        "}"
        : "=f"(r.x), "=f"(r.y) : "d"(s));
    return r;
}

// ---------------------------------------------------------------------------
// Fused projection kernel.
//   blocks [0,256):    g_Wq[row][e] = Q[row]·W1[:,e] + b1[e]
//   blocks [256,512):  g_Wk[row][e] = K[row]·W2[:,e] + b2[e]
// 32 rows per block; W (16KB) + padded X tile (8.3KB) in smem; FMA-bound.
// Output staged through smem so STGs are coalesced.
// ---------------------------------------------------------------------------
__global__ __launch_bounds__(256) void proj_fused_kernel(
    const float* __restrict__ Q, const float* __restrict__ K,
    const float* __restrict__ W1, const float* __restrict__ b1,
    const float* __restrict__ W2, const float* __restrict__ b2)
{
    __shared__ float Ws[DD][DD];
    __shared__ float Xs[32][DD + 1];

    const int  tid  = threadIdx.x;
    const bool isK  = (blockIdx.x >= 256);
    const int  blk  = isK ? (blockIdx.x - 256) : blockIdx.x;
    const int  rowBase = blk * 32;

    const float* __restrict__ X  = isK ? K  : Q;
    const float* __restrict__ W  = isK ? W2 : W1;
    const float* __restrict__ bb = isK ? b2 : b1;
    float* __restrict__ Out      = isK ? g_Wk : g_Wq;

    {
        const float4* src = (const float4*)W;
        float4* dst = (float4*)&Ws[0][0];
#pragma unroll
        for (int t = 0; t < 4; t++) dst[tid + t * 256] = src[tid + t * 256];
    }
#pragma unroll
    for (int t = 0; t < 8; t++) {
        int i = tid + t * 256;
        int r = i >> 6, c = i & 63;
        Xs[r][c] = X[(size_t)(rowBase + r) * DD + c];
    }
    __syncthreads();

    const int lane = tid & 31;   // row within tile
    const int eg   = tid >> 5;   // e-group of 8

    float acc[8];
#pragma unroll
    for (int j = 0; j < 8; j++) acc[j] = __ldg(&bb[eg * 8 + j]);

#pragma unroll
    for (int d = 0; d < DD; d++) {
        const float xv = Xs[lane][d];                        // pad 65: conflict-free
        const float4 w0 = *(const float4*)&Ws[d][eg * 8];    // broadcast
        const float4 w1 = *(const float4*)&Ws[d][eg * 8 + 4];
        acc[0] += xv * w0.x; acc[1] += xv * w0.y;
        acc[2] += xv * w0.z; acc[3] += xv * w0.w;
        acc[4] += xv * w1.x; acc[5] += xv * w1.y;
        acc[6] += xv * w1.z; acc[7] += xv * w1.w;
    }

    __syncthreads();
#pragma unroll
    for (int j = 0; j < 8; j++) Xs[lane][eg * 8 + j] = acc[j];
    __syncthreads();
#pragma unroll
    for (int t = 0; t < 8; t++) {
        int i = tid + t * 256;
        int r = i >> 6, c = i & 63;
        Out[(size_t)(rowBase + r) * DD + c] = Xs[r][c];      // coalesced
    }
}

// ---------------------------------------------------------------------------
// Main kernel: scores[bh][q][k] = sum_d tanh(wq[q][d] + wk[k][d]) * v[d] + bV
// 256 threads, tile 32q x 128k, 4x4 micro-tile; thread tx owns k = j*32+tx.
// Per 2 elements: 1 FADD2 + 1 cvt + 1 MUFU(tanh.f16x2) + 2 cvt + 2 FFMA.
// MUFU-bound at HALF the f32 MUFU count.
// ---------------------------------------------------------------------------
__global__ __launch_bounds__(256) void attn_main_kernel(
    const float* __restrict__ Vv, const float* __restrict__ bV,
    float* __restrict__ out)
{
    __shared__ float wq_s[TQ][DD];     // 8 KB, broadcast reads
    __shared__ float wk_s[TK][WKP];    // 34.8 KB, k-major, pad 68
    __shared__ float v_s[DD];

    const int bh    = blockIdx.z;
    const int qBase = blockIdx.y * TQ;
    const int kBase = blockIdx.x * TK;
    const int tid   = threadIdx.x;

    // wq tile: coalesced float4 copy
    {
        const float4* src = (const float4*)(g_Wq + (size_t)(bh * LQ + qBase) * DD);
        float4* dst = (float4*)&wq_s[0][0];
        for (int i = tid; i < TQ * DD / 4; i += 256) dst[i] = src[i];
    }
    // wk tile: 128 rows x 16 float4, coalesced reads, aligned padded stores
#pragma unroll
    for (int t = 0; t < 8; t++) {
        int i = tid + t * 256;          // 2048 float4s
        int k = i >> 4, c = i & 15;
        *(float4*)&wk_s[k][c * 4] =
            ((const float4*)(g_Wk + (size_t)(bh * LK + kBase + k) * DD))[c];
    }
    if (tid < DD) v_s[tid] = Vv[tid];
    __syncthreads();

    const int ty = tid >> 5;            // q group (warp id)
    const int tx = tid & 31;            // k lane; k = j*32 + tx

    float acc[4][4];
#pragma unroll
    for (int i = 0; i < 4; i++)
#pragma unroll
        for (int j = 0; j < 4; j++) acc[i][j] = 0.0f;

#pragma unroll 4
    for (int d = 0; d < DD; d += 4) {
        double2 wq2[4];                 // .x = d0d1, .y = d2d3 (f32 pairs)
#pragma unroll
        for (int i = 0; i < 4; i++)
            wq2[i] = *(const double2*)&wq_s[ty * 4 + i][d];      // broadcast
        double2 wk2[4];
#pragma unroll
        for (int j = 0; j < 4; j++)
            wk2[j] = *(const double2*)&wk_s[j * 32 + tx][d];     // conflict-free
        const float4 v4 = *(const float4*)&v_s[d];

#pragma unroll
        for (int i = 0; i < 4; i++) {
#pragma unroll
            for (int j = 0; j < 4; j++) {
                float2 t01 = tanh2_f16(add_f32x2(wq2[i].x, wk2[j].x));
                acc[i][j] = fmaf(t01.x, v4.x, acc[i][j]);
                acc[i][j] = fmaf(t01.y, v4.y, acc[i][j]);
                float2 t23 = tanh2_f16(add_f32x2(wq2[i].y, wk2[j].y));
                acc[i][j] = fmaf(t23.x, v4.z, acc[i][j]);
                acc[i][j] = fmaf(t23.y, v4.w, acc[i][j]);
            }
        }
    }

    const float bv = bV[0];
#pragma unroll
    for (int i = 0; i < 4; i++) {
        const size_t rowOff = (size_t)(bh * LQ + qBase + ty * 4 + i) * LK + kBase;
#pragma unroll
        for (int j = 0; j < 4; j++)
            out[rowOff + j * 32 + tx] = acc[i][j] + bv;   // lanes consecutive: coalesced
    }
}

// ---------------------------------------------------------------------------
// Launch
// ---------------------------------------------------------------------------
extern "C" void kernel_launch(void* const* d_in, const int* in_sizes, int n_in,
                              void* d_out, int out_size)
{
    const float* Q  = (const float*)d_in[0];
    const float* K  = (const float*)d_in[1];
    const float* W1 = (const float*)d_in[2];
    const float* b1 = (const float*)d_in[3];
    const float* W2 = (const float*)d_in[4];
    const float* b2 = (const float*)d_in[5];
    const float* V  = (const float*)d_in[6];
    const float* bV = (const float*)d_in[7];
    float* out = (float*)d_out;

    proj_fused_kernel<<<512, 256>>>(Q, K, W1, b1, W2, b2);

    dim3 grid(LK / TK, LQ / TQ, BH);
    attn_main_kernel<<<grid, 256>>>(V, bV, out);
}

// round 5
// speedup vs baseline: 1.0214x; 1.0214x over previous
#include <cuda_runtime.h>
#include <cuda_fp16.h>

#define BH   16
#define LQ   512
#define LK   512
#define DD   64
#define TQ   32
#define TK   128
#define WKW  33   // wk row width in u32 (66 halves): odd stride -> conflict-free

// Projected tensors in fp16, row-major [row][d].
// Declared as __half2 so the base is 4B-aligned for u32 access.
__device__ __half2 g_Wq_h[BH * LQ * DD / 2];
__device__ __half2 g_Wk_h[BH * LK * DD / 2];

// ---------------------------------------------------------------------------
// 2 tanhs in one MUFU op.
// ---------------------------------------------------------------------------
__device__ __forceinline__ __half2 tanh2(__half2 x) {
    unsigned xi = *(unsigned*)&x, yi;
    asm("tanh.approx.f16x2 %0, %1;" : "=r"(yi) : "r"(xi));
    return *(__half2*)&yi;
}

// ---------------------------------------------------------------------------
// Widen f16x2 partial and add into an f32-pair accumulator:
// 2x cvt + 1x add.rn.f32x2 (one FMA-pipe op for both lanes).
// ---------------------------------------------------------------------------
__device__ __forceinline__ void acc_flush(double& acc, __half2 h) {
    unsigned hi = *(unsigned*)&h;
    asm("{\n\t"
        ".reg .f16 l, m;\n\t"
        ".reg .f32 fl, fh;\n\t"
        ".reg .b64 p;\n\t"
        "mov.b32 {l, m}, %1;\n\t"
        "cvt.f32.f16 fl, l;\n\t"
        "cvt.f32.f16 fh, m;\n\t"
        "mov.b64 p, {fl, fh};\n\t"
        "add.rn.f32x2 %0, %0, p;\n\t"
        "}" : "+d"(acc) : "r"(hi));
}

// ---------------------------------------------------------------------------
// Fused projection kernel (fp32 compute, fp16 output).
//   blocks [0,256):    g_Wq_h[row][e] = Q[row]·W1[:,e] + b1[e]
//   blocks [256,512):  g_Wk_h[row][e] = K[row]·W2[:,e] + b2[e]
// ---------------------------------------------------------------------------
__global__ __launch_bounds__(256) void proj_fused_kernel(
    const float* __restrict__ Q, const float* __restrict__ K,
    const float* __restrict__ W1, const float* __restrict__ b1,
    const float* __restrict__ W2, const float* __restrict__ b2)
{
    __shared__ float Ws[DD][DD];
    __shared__ float Xs[32][DD + 1];

    const int  tid  = threadIdx.x;
    const bool isK  = (blockIdx.x >= 256);
    const int  blk  = isK ? (blockIdx.x - 256) : blockIdx.x;
    const int  rowBase = blk * 32;

    const float* __restrict__ X  = isK ? K  : Q;
    const float* __restrict__ W  = isK ? W2 : W1;
    const float* __restrict__ bb = isK ? b2 : b1;
    __half2* __restrict__ OutH   = isK ? g_Wk_h : g_Wq_h;

    {
        const float4* src = (const float4*)W;
        float4* dst = (float4*)&Ws[0][0];
#pragma unroll
        for (int t = 0; t < 4; t++) dst[tid + t * 256] = src[tid + t * 256];
    }
#pragma unroll
    for (int t = 0; t < 8; t++) {
        int i = tid + t * 256;
        int r = i >> 6, c = i & 63;
        Xs[r][c] = X[(size_t)(rowBase + r) * DD + c];
    }
    __syncthreads();

    const int lane = tid & 31;   // row within tile
    const int eg   = tid >> 5;   // e-group of 8

    float acc[8];
#pragma unroll
    for (int j = 0; j < 8; j++) acc[j] = __ldg(&bb[eg * 8 + j]);

#pragma unroll
    for (int d = 0; d < DD; d++) {
        const float xv = Xs[lane][d];
        const float4 w0 = *(const float4*)&Ws[d][eg * 8];
        const float4 w1 = *(const float4*)&Ws[d][eg * 8 + 4];
        acc[0] += xv * w0.x; acc[1] += xv * w0.y;
        acc[2] += xv * w0.z; acc[3] += xv * w0.w;
        acc[4] += xv * w1.x; acc[5] += xv * w1.y;
        acc[6] += xv * w1.z; acc[7] += xv * w1.w;
    }

    __syncthreads();
#pragma unroll
    for (int j = 0; j < 8; j++) Xs[lane][eg * 8 + j] = acc[j];
    __syncthreads();

    // Convert + store as half2, coalesced (32 rows x 32 half2 per block).
#pragma unroll
    for (int t = 0; t < 4; t++) {
        int i = tid + t * 256;
        int r = i >> 5, c = i & 31;
        __half2 hv = __floats2half2_rn(Xs[r][2 * c], Xs[r][2 * c + 1]);
        OutH[(size_t)(rowBase + r) * (DD / 2) + c] = hv;
    }
}

// ---------------------------------------------------------------------------
// Main kernel: scores[bh][q][k] = sum_d tanh(wq[q][d] + wk[k][d]) * v[d] + bV
// Full fp16x2 pipeline: HADD2 -> MUFU tanh.f16x2 -> HMUL2/HFMA2(xv) ->
// widen+add.f32x2 per 4 d's.  ~2.25 instr per element; MUFU-bound at
// 0.5 MUFU-slot/element.
// ---------------------------------------------------------------------------
__global__ __launch_bounds__(256, 3) void attn_main_kernel(
    const float* __restrict__ Vv, const float* __restrict__ bV,
    float* __restrict__ out)
{
    __shared__ __half2 wq_s[TQ * (DD / 2)];     // 4 KB, broadcast reads
    __shared__ unsigned wk_s[TK * WKW];         // 16.9 KB, odd stride: conflict-free
    __shared__ __half2 v_s[DD / 2];

    const int bh    = blockIdx.z;
    const int qBase = blockIdx.y * TQ;
    const int kBase = blockIdx.x * TK;
    const int tid   = threadIdx.x;

    // wq tile: 32 rows x 32 u32 = 1024 u32, coalesced
    {
        const unsigned* src = (const unsigned*)(g_Wq_h + (size_t)(bh * LQ + qBase) * (DD / 2));
        unsigned* dst = (unsigned*)wq_s;
#pragma unroll
        for (int t = 0; t < 4; t++) dst[tid + t * 256] = src[tid + t * 256];
    }
    // wk tile: 128 rows x 32 u32 = 4096 u32 -> padded rows of 33 u32
    {
        const unsigned* src = (const unsigned*)(g_Wk_h + (size_t)(bh * LK + kBase) * (DD / 2));
#pragma unroll
        for (int t = 0; t < 16; t++) {          // 16*256 = 4096 (FIX: was 8)
            int i = tid + t * 256;
            int k = i >> 5, c = i & 31;
            wk_s[k * WKW + c] = src[k * 32 + c];
        }
    }
    if (tid < DD / 2)
        v_s[tid] = __floats2half2_rn(Vv[2 * tid], Vv[2 * tid + 1]);
    __syncthreads();

    const int ty = tid >> 5;            // q group (warp id)
    const int tx = tid & 31;            // k lane; k = j*32 + tx

    double acc[4][4];                   // f32-pair accumulators
#pragma unroll
    for (int i = 0; i < 4; i++)
#pragma unroll
        for (int j = 0; j < 4; j++) acc[i][j] = 0.0;

#pragma unroll 4
    for (int d = 0; d < DD; d += 4) {
        const __half2 v01 = v_s[d / 2];
        const __half2 v23 = v_s[d / 2 + 1];

        __half2 wq01[4], wq23[4];
#pragma unroll
        for (int i = 0; i < 4; i++) {
            const __half2* row = &wq_s[(ty * 4 + i) * (DD / 2) + d / 2];
            wq01[i] = row[0];           // broadcast
            wq23[i] = row[1];
        }
        __half2 wk01[4], wk23[4];
#pragma unroll
        for (int j = 0; j < 4; j++) {
            const unsigned* row = &wk_s[(j * 32 + tx) * WKW + d / 2];
            unsigned a = row[0], b = row[1];   // scalar LDS: conflict-free
            wk01[j] = *(__half2*)&a;
            wk23[j] = *(__half2*)&b;
        }

#pragma unroll
        for (int i = 0; i < 4; i++) {
#pragma unroll
            for (int j = 0; j < 4; j++) {
                __half2 t01 = tanh2(__hadd2(wq01[i], wk01[j]));
                __half2 t23 = tanh2(__hadd2(wq23[i], wk23[j]));
                __half2 h   = __hfma2(t23, v23, __hmul2(t01, v01));
                acc_flush(acc[i][j], h);
            }
        }
    }

    const float bv = bV[0];
#pragma unroll
    for (int i = 0; i < 4; i++) {
        const size_t rowOff = (size_t)(bh * LQ + qBase + ty * 4 + i) * LK + kBase;
#pragma unroll
        for (int j = 0; j < 4; j++) {
            float2 a = *(float2*)&acc[i][j];
            out[rowOff + j * 32 + tx] = a.x + a.y + bv;   // coalesced
        }
    }
}

// ---------------------------------------------------------------------------
// Launch
// ---------------------------------------------------------------------------
extern "C" void kernel_launch(void* const* d_in, const int* in_sizes, int n_in,
                              void* d_out, int out_size)
{
    const float* Q  = (const float*)d_in[0];
    const float* K  = (const float*)d_in[1];
    const float* W1 = (const float*)d_in[2];
    const float* b1 = (const float*)d_in[3];
    const float* W2 = (const float*)d_in[4];
    const float* b2 = (const float*)d_in[5];
    const float* V  = (const float*)d_in[6];
    const float* bV = (const float*)d_in[7];
    float* out = (float*)d_out;

    proj_fused_kernel<<<512, 256>>>(Q, K, W1, b1, W2, b2);

    dim3 grid(LK / TK, LQ / TQ, BH);
    attn_main_kernel<<<grid, 256>>>(V, bV, out);
}